// round 14
// baseline (speedup 1.0000x reference)
#include <cuda_runtime.h>
#include <cuda_bf16.h>
#include <cstdint>
#include <math.h>

// Problem constants
static constexpr int Bn  = 512;    // batch
static constexpr int Nn  = 8192;   // pool
static constexpr int Dn  = 1024;   // pool dim
static constexpr int DAn = 512;    // z dim
static constexpr int Sn  = 8;      // aspects
static constexpr int DKn = 64;     // head dim
static constexpr int Jn  = Sn * DKn; // 512 flattened key/query dim

// ---------------------------------------------------------------------------
// Scratch (device globals; no allocation allowed)
// ---------------------------------------------------------------------------
__device__ __nv_bfloat16 g_BhT[Jn * Dn];   // W_K^T hi  [512,1024]
__device__ __nv_bfloat16 g_BlT[Jn * Dn];   // W_K^T lo
__device__ __nv_bfloat16 g_WQh[Jn * DAn];  // W_Q^T hi  [512,512]
__device__ __nv_bfloat16 g_WQl[Jn * DAn];
__device__ __nv_bfloat16 g_Qh[Bn * Jn];    // weighted normalized queries hi
__device__ __nv_bfloat16 g_Ql[Bn * Jn];
__device__ __nv_bfloat16 g_Kh[Nn * Jn];    // normalized keys hi [8192,512]
__device__ __nv_bfloat16 g_Kl[Nn * Jn];
__device__ float         g_qraw[Bn * Jn];  // raw queries fp32 (discarded)

// ---------------------------------------------------------------------------
// helpers
// ---------------------------------------------------------------------------
__device__ __forceinline__ uint32_t smem_to_u32(const void* smem_ptr) {
    uint32_t addr;
    asm("{ .reg .u64 tmp; cvta.to.shared.u64 tmp, %1; cvt.u32.u64 %0, tmp; }"
        : "=r"(addr) : "l"(smem_ptr));
    return addr;
}

__device__ __forceinline__ void cp16(uint32_t dst, const void* src) {
    asm volatile("cp.async.cg.shared.global [%0], [%1], 16;"
                 :: "r"(dst), "l"(src) : "memory");
}
#define CP_COMMIT() asm volatile("cp.async.commit_group;" ::: "memory")
#define CP_WAIT(n)  asm volatile("cp.async.wait_group %0;" :: "n"(n) : "memory")

__device__ __forceinline__ void ldsm_x4(uint32_t* r, uint32_t addr) {
    asm volatile("ldmatrix.sync.aligned.m8n8.x4.shared.b16 {%0,%1,%2,%3}, [%4];"
                 : "=r"(r[0]), "=r"(r[1]), "=r"(r[2]), "=r"(r[3]) : "r"(addr));
}

__device__ __forceinline__ void mma_bf16(float* c, const uint32_t* a, const uint32_t* b) {
    asm volatile(
        "mma.sync.aligned.m16n8k16.row.col.f32.bf16.bf16.f32 "
        "{%0,%1,%2,%3}, {%4,%5,%6,%7}, {%8,%9}, {%0,%1,%2,%3};"
        : "+f"(c[0]), "+f"(c[1]), "+f"(c[2]), "+f"(c[3])
        : "r"(a[0]), "r"(a[1]), "r"(a[2]), "r"(a[3]), "r"(b[0]), "r"(b[1]));
}

__device__ __forceinline__ void sts64(uint32_t addr, uint32_t a, uint32_t b) {
    asm volatile("st.shared.v2.b32 [%0], {%1,%2};" :: "r"(addr), "r"(a), "r"(b) : "memory");
}

#define SWZ(off) ((off) ^ (((off) >> 3) & 0x70))

__device__ __forceinline__ void bf16_split(float v, __nv_bfloat16& h, __nv_bfloat16& l) {
    h = __float2bfloat16(v);
    l = __float2bfloat16(v - __bfloat162float(h));
}

// ---------------------------------------------------------------------------
// K0T2: fused transpose+split of BOTH weight tensors.
// grid (Sn, 24): y<8 -> W_Q (D=512) tile y ; y>=8 -> W_K (D=1024) tile y-8.
// ---------------------------------------------------------------------------
__global__ void __launch_bounds__(256) k_split_T2(
    const float* __restrict__ WQ, __nv_bfloat16* __restrict__ QH,
    __nv_bfloat16* __restrict__ QL,
    const float* __restrict__ WK, __nv_bfloat16* __restrict__ KH,
    __nv_bfloat16* __restrict__ KL)
{
    __shared__ float tile[64][65];
    int a  = blockIdx.x;
    int y  = blockIdx.y;
    const float* W; __nv_bfloat16 *H, *L; int D, p0;
    if (y < DAn / 64) { W = WQ; H = QH; L = QL; D = DAn; p0 = y * 64; }
    else              { W = WK; H = KH; L = KL; D = Dn;  p0 = (y - DAn / 64) * 64; }

    int t  = threadIdx.x;
    int q  = t & 63, rr = t >> 6;

    const float* src = W + (size_t)a * (D * DKn) + (size_t)p0 * DKn;
#pragma unroll
    for (int pi = rr; pi < 64; pi += 4)
        tile[pi][q] = src[pi * DKn + q];
    __syncthreads();

    int pi = t & 63, qb = t >> 6;
#pragma unroll
    for (int qq = qb; qq < 64; qq += 4) {
        float v = tile[pi][qq];
        __nv_bfloat16 h, l;
        bf16_split(v, h, l);
        size_t off = (size_t)(a * 64 + qq) * D + p0 + pi;
        H[off] = h;
        L[off] = l;
    }
}

// ---------------------------------------------------------------------------
// Split-3 bf16 GEMM body on mma.sync:
//   C[M,N] = Ah*Bh^T + Al*Bh^T + Ah*Bl^T
// CFG=1: 64x128 tile, 256 thr (8 warps 4m x 2n), warp 16x64. 96KB smem
//        -> 2 CTAs/SM co-residency (hides barrier/cp.async bubbles).
// BK=64, 2-stage cp.async double buffer, SW128 swizzle.
// CVT_A:  A read as fp32, split to bf16 hi/lo in-kernel.
// FUSE_NORM: L2-normalize each row's 64-wide aspect block (== warpN block);
//         Wv (if non-null) = RAW aspect logits, softmax inline.
// ---------------------------------------------------------------------------
template <int CFG, bool FUSE_NORM, bool CVT_A>
__device__ __forceinline__ void gemm_body(
    const float* __restrict__ A32,
    const __nv_bfloat16* __restrict__ Ah, const __nv_bfloat16* __restrict__ Al,
    const __nv_bfloat16* __restrict__ Bh, const __nv_bfloat16* __restrict__ Bl,
    float* __restrict__ C, int Ktot, int ldC,
    __nv_bfloat16* __restrict__ Kh, __nv_bfloat16* __restrict__ Kl,
    const float* __restrict__ Wv,
    int m0, int n0, uint8_t* smem)
{
    constexpr int THREADS = CFG == 0 ? 512 : (CFG == 1 ? 256 : 128);
    constexpr int MI      = CFG == 0 ? 2 : 1;
    constexpr int M_TILE  = CFG == 0 ? 128 : 64;
    constexpr int N_TILE  = CFG == 0 ? 256 : (CFG == 1 ? 128 : 64);
    constexpr uint32_t AT     = M_TILE * 128;
    constexpr uint32_t BT     = N_TILE * 128;
    constexpr uint32_t OFF_AL = AT;
    constexpr uint32_t OFF_BH = 2 * AT;
    constexpr uint32_t OFF_BL = 2 * AT + BT;
    constexpr uint32_t STAGE  = 2 * AT + 2 * BT;

    const int t    = threadIdx.x;
    const int lane = t & 31;
    const int wid  = t >> 5;
    const int warpM = wid & 3;
    const int warpN = wid >> 2;

    const uint32_t smem_u = smem_to_u32(smem);

    auto loadB = [&](int kt, int s) {
        uint32_t base = smem_u + (uint32_t)s * STAGE;
        int koff = kt * 64;
#pragma unroll
        for (int i = 0; i < (N_TILE * 8) / THREADS; i++) {
            int c   = t + i * THREADS;
            int row = c >> 3, grp = c & 7;
            uint32_t soff = SWZ((uint32_t)(row * 128 + grp * 16));
            size_t boff = (size_t)(n0 + row) * Ktot + koff + grp * 8;
            cp16(base + OFF_BH + soff, Bh + boff);
            cp16(base + OFF_BL + soff, Bl + boff);
        }
    };

    auto loadA_bf16 = [&](int kt, int s) {
        uint32_t base = smem_u + (uint32_t)s * STAGE;
        int koff = kt * 64;
#pragma unroll
        for (int i = 0; i < (M_TILE * 8) / THREADS; i++) {
            int c   = t + i * THREADS;
            int row = c >> 3, grp = c & 7;
            uint32_t soff = SWZ((uint32_t)(row * 128 + grp * 16));
            size_t aoff = (size_t)(m0 + row) * Ktot + koff + grp * 8;
            cp16(base + soff,          Ah + aoff);
            cp16(base + OFF_AL + soff, Al + aoff);
        }
    };

    constexpr int NAV = (M_TILE * 16) / THREADS;
    float4 av[NAV];
    auto ldgA = [&](int kt) {
#pragma unroll
        for (int i = 0; i < NAV; i++) {
            int c = t + i * THREADS;
            int row = c >> 4, f4 = c & 15;
            av[i] = *(const float4*)(A32 + (size_t)(m0 + row) * Ktot + kt * 64 + f4 * 4);
        }
    };
    auto cvtstsA = [&](int s) {
        uint32_t base = smem_u + (uint32_t)s * STAGE;
#pragma unroll
        for (int i = 0; i < NAV; i++) {
            int c = t + i * THREADS;
            int row = c >> 4, f4 = c & 15;
            uint32_t so = SWZ((uint32_t)(row * 128 + f4 * 8));
            __nv_bfloat16 h0,l0,h1,l1,h2,l2,h3,l3;
            bf16_split(av[i].x, h0, l0); bf16_split(av[i].y, h1, l1);
            bf16_split(av[i].z, h2, l2); bf16_split(av[i].w, h3, l3);
            __nv_bfloat162 pA, pB;
            pA.x = h0; pA.y = h1; pB.x = h2; pB.y = h3;
            uint32_t hx = *(uint32_t*)&pA, hy = *(uint32_t*)&pB;
            pA.x = l0; pA.y = l1; pB.x = l2; pB.y = l3;
            uint32_t lx = *(uint32_t*)&pA, ly = *(uint32_t*)&pB;
            sts64(base + so,          hx, hy);
            sts64(base + OFF_AL + so, lx, ly);
        }
    };

    const int arow  = warpM * (16 * MI) + (lane & 15);
    const int acolg = (lane >> 4) * 16;
    const int bg    = lane >> 3;
    const int brow  = warpN * 64 + ((bg >= 2) ? 8 : 0) + (lane & 7);
    const int bcol  = (bg & 1) * 16;

    float acc[MI][8][4];
#pragma unroll
    for (int mi = 0; mi < MI; mi++)
#pragma unroll
        for (int nj = 0; nj < 8; nj++)
#pragma unroll
            for (int r = 0; r < 4; r++) acc[mi][nj][r] = 0.f;

    const int KT = Ktot >> 6;

    if (CVT_A) {
        ldgA(0);
        cvtstsA(0);
        loadB(0, 0);
    } else {
        loadA_bf16(0, 0);
        loadB(0, 0);
    }
    CP_COMMIT();

    for (int kt = 0; kt < KT; kt++) {
        if (kt + 1 < KT) {
            if (CVT_A) {
                ldgA(kt + 1);
                loadB(kt + 1, (kt + 1) & 1);
            } else {
                loadA_bf16(kt + 1, (kt + 1) & 1);
                loadB(kt + 1, (kt + 1) & 1);
            }
            CP_COMMIT();
            CP_WAIT(1);
        } else {
            CP_WAIT(0);
        }
        __syncthreads();

        uint32_t base = smem_u + (uint32_t)(kt & 1) * STAGE;

#pragma unroll
        for (int ks = 0; ks < 4; ks++) {
            uint32_t ah[MI][4], al[MI][4];
#pragma unroll
            for (int mi = 0; mi < MI; mi++) {
                uint32_t off = SWZ((uint32_t)((arow + mi * 16) * 128 + ks * 32 + acolg));
                ldsm_x4(ah[mi], base + off);
                ldsm_x4(al[mi], base + OFF_AL + off);
            }
#pragma unroll
            for (int njp = 0; njp < 4; njp++) {
                uint32_t bh[4], bl[4];
                uint32_t off = SWZ((uint32_t)((brow + njp * 16) * 128 + ks * 32 + bcol));
                ldsm_x4(bh, base + OFF_BH + off);
                ldsm_x4(bl, base + OFF_BL + off);
#pragma unroll
                for (int half = 0; half < 2; half++) {
                    int nj = njp * 2 + half;
                    const uint32_t* bhf = &bh[half * 2];
                    const uint32_t* blf = &bl[half * 2];
#pragma unroll
                    for (int mi = 0; mi < MI; mi++) {
                        mma_bf16(acc[mi][nj], ah[mi], bhf);
                        mma_bf16(acc[mi][nj], al[mi], bhf);
                        mma_bf16(acc[mi][nj], ah[mi], blf);
                    }
                }
            }
        }

        if (CVT_A && kt + 1 < KT) cvtstsA((kt + 1) & 1);
        __syncthreads();
    }

    // --- epilogue ---
    float wa = 1.f;
    if (FUSE_NORM && Wv != nullptr) {
        int aspect = (n0 + warpN * 64) >> 6;
        float m = Wv[0];
#pragma unroll
        for (int i = 1; i < Sn; i++) m = fmaxf(m, Wv[i]);
        float s = 0.f, ea = 0.f;
#pragma unroll
        for (int i = 0; i < Sn; i++) {
            float e = __expf(Wv[i] - m);
            s += e;
            if (i == aspect) ea = e;
        }
        wa = ea / s;
    }

#pragma unroll
    for (int mi = 0; mi < MI; mi++) {
        int r0 = m0 + warpM * (16 * MI) + mi * 16 + (lane >> 2);
        int r1 = r0 + 8;
        int colb = n0 + warpN * 64 + (lane & 3) * 2;

        float inv0 = 1.f, inv1 = 1.f;
        if (FUSE_NORM) {
            float s0 = 0.f, s1 = 0.f;
#pragma unroll
            for (int nj = 0; nj < 8; nj++) {
                s0 = fmaf(acc[mi][nj][0], acc[mi][nj][0], s0);
                s0 = fmaf(acc[mi][nj][1], acc[mi][nj][1], s0);
                s1 = fmaf(acc[mi][nj][2], acc[mi][nj][2], s1);
                s1 = fmaf(acc[mi][nj][3], acc[mi][nj][3], s1);
            }
            s0 += __shfl_xor_sync(0xffffffffu, s0, 1);
            s0 += __shfl_xor_sync(0xffffffffu, s0, 2);
            s1 += __shfl_xor_sync(0xffffffffu, s1, 1);
            s1 += __shfl_xor_sync(0xffffffffu, s1, 2);
            inv0 = wa / (sqrtf(s0) + 1e-8f);
            inv1 = wa / (sqrtf(s1) + 1e-8f);
        }

#pragma unroll
        for (int nj = 0; nj < 8; nj++) {
            int col = colb + nj * 8;
            *(float2*)&C[(size_t)r0 * ldC + col] = make_float2(acc[mi][nj][0], acc[mi][nj][1]);
            *(float2*)&C[(size_t)r1 * ldC + col] = make_float2(acc[mi][nj][2], acc[mi][nj][3]);
            if (FUSE_NORM) {
                __nv_bfloat16 h0, l0, h1, l1;
                __nv_bfloat162 hh, ll;
                bf16_split(acc[mi][nj][0] * inv0, h0, l0);
                bf16_split(acc[mi][nj][1] * inv0, h1, l1);
                hh.x = h0; hh.y = h1; ll.x = l0; ll.y = l1;
                *(__nv_bfloat162*)&Kh[(size_t)r0 * ldC + col] = hh;
                *(__nv_bfloat162*)&Kl[(size_t)r0 * ldC + col] = ll;
                bf16_split(acc[mi][nj][2] * inv1, h0, l0);
                bf16_split(acc[mi][nj][3] * inv1, h1, l1);
                hh.x = h0; hh.y = h1; ll.x = l0; ll.y = l1;
                *(__nv_bfloat162*)&Kh[(size_t)r1 * ldC + col] = hh;
                *(__nv_bfloat162*)&Kl[(size_t)r1 * ldC + col] = ll;
            }
        }
    }
}

// ---------------------------------------------------------------------------
// Fused GEMM1 + GEMM0 launch (both CFG1/FUSE_NORM/CVT_A; 544 blocks, 256thr,
// 96KB smem -> 2 CTAs/SM):
//   blocks [0,512):   GEMM1 keys  = pool @ WkT^T  (4 n-tiles x 128 m-tiles)
//   blocks [512,544): GEMM0 query = z    @ WQT^T  (4 n-tiles x   8 m-tiles)
// ---------------------------------------------------------------------------
__global__ void __launch_bounds__(256) k_gemm01(
    const float* __restrict__ pool, const float* __restrict__ z,
    const __nv_bfloat16* __restrict__ BhT, const __nv_bfloat16* __restrict__ BlT,
    const __nv_bfloat16* __restrict__ WQh, const __nv_bfloat16* __restrict__ WQl,
    float* __restrict__ keys, float* __restrict__ qraw,
    __nv_bfloat16* __restrict__ Kh, __nv_bfloat16* __restrict__ Kl,
    __nv_bfloat16* __restrict__ Qh, __nv_bfloat16* __restrict__ Ql,
    const float* __restrict__ logits)
{
    extern __shared__ __align__(1024) uint8_t smem[];
    int b = blockIdx.x;
    const float* A32; const __nv_bfloat16 *Bh, *Bl; float* C;
    __nv_bfloat16 *KH, *KL; const float* Wv;
    int Ktot, m0, n0;
    if (b < 512) {          // GEMM1
        A32 = pool; Bh = BhT; Bl = BlT; C = keys; KH = Kh; KL = Kl;
        Wv = nullptr; Ktot = Dn;
        n0 = (b & 3) * 128; m0 = (b >> 2) * 64;
    } else {                // GEMM0
        int b2 = b - 512;
        A32 = z; Bh = WQh; Bl = WQl; C = qraw; KH = Qh; KL = Ql;
        Wv = logits; Ktot = DAn;
        n0 = (b2 & 3) * 128; m0 = (b2 >> 2) * 64;
    }
    gemm_body<1, true, true>(A32, nullptr, nullptr, Bh, Bl, C, Ktot, Jn,
                             KH, KL, Wv, m0, n0, smem);
}

// ---------------------------------------------------------------------------
// GEMM2: scores = Qt @ Khat^T (bf16 operands). grid (64, 8), 256 thr, 96KB.
// ---------------------------------------------------------------------------
__global__ void __launch_bounds__(256) k_gemm2(
    const __nv_bfloat16* __restrict__ Qh, const __nv_bfloat16* __restrict__ Ql,
    const __nv_bfloat16* __restrict__ Kh, const __nv_bfloat16* __restrict__ Kl,
    float* __restrict__ scores)
{
    extern __shared__ __align__(1024) uint8_t smem[];
    int m0 = blockIdx.y * 64;
    int n0 = blockIdx.x * 128;
    gemm_body<1, false, false>(nullptr, Qh, Ql, Kh, Kl, scores, Jn, Nn,
                               nullptr, nullptr, nullptr, m0, n0, smem);
}

// ---------------------------------------------------------------------------
// K5: gate + temperature-scaled normalize -> alpha. One block per batch row.
// Register-resident: 8 float4 per thread (8192 elems / 256 thr), no smem raw.
// ---------------------------------------------------------------------------
__global__ void __launch_bounds__(256) k_alpha(
    const float* __restrict__ scores, float* __restrict__ alpha,
    const float* __restrict__ ptau, const float* __restrict__ plam,
    const float* __restrict__ ptemp)
{
    __shared__ float red[8];
    __shared__ float stot;

    int t = threadIdx.x, b = blockIdx.x;
    float tau = *ptau, lam = *plam, invT = 1.f / (*ptemp);

    float4 rv[8];
    float s_local = 0.f;
    const float4* src = (const float4*)(scores + (size_t)b * Nn);
#pragma unroll
    for (int i = 0; i < 8; i++) {
        float4 s4 = src[t + i * 256];
        rv[i].x = __expf(s4.x * invT) / (1.f + __expf(-lam * (s4.x - tau)));
        rv[i].y = __expf(s4.y * invT) / (1.f + __expf(-lam * (s4.y - tau)));
        rv[i].z = __expf(s4.z * invT) / (1.f + __expf(-lam * (s4.z - tau)));
        rv[i].w = __expf(s4.w * invT) / (1.f + __expf(-lam * (s4.w - tau)));
        s_local += (rv[i].x + rv[i].y) + (rv[i].z + rv[i].w);
    }
#pragma unroll
    for (int off = 16; off > 0; off >>= 1)
        s_local += __shfl_xor_sync(0xffffffffu, s_local, off);
    if ((t & 31) == 0) red[t >> 5] = s_local;
    __syncthreads();
    if (t == 0) {
        float s = 0.f;
        for (int w = 0; w < 8; w++) s += red[w];
        stot = s;
    }
    __syncthreads();

    float inv = 1.f / (stot + 1e-8f);
    float4* dst = (float4*)(alpha + (size_t)b * Nn);
#pragma unroll
    for (int i = 0; i < 8; i++)
        dst[t + i * 256] = make_float4(rv[i].x * inv, rv[i].y * inv,
                                       rv[i].z * inv, rv[i].w * inv);
}

// ---------------------------------------------------------------------------
extern "C" void kernel_launch(void* const* d_in, const int* in_sizes, int n_in,
                              void* d_out, int out_size)
{
    const float* z      = (const float*)d_in[0];
    const float* pool   = (const float*)d_in[1];
    const float* WQ     = (const float*)d_in[2];
    const float* WK     = (const float*)d_in[3];
    const float* logits = (const float*)d_in[4];
    const float* tau    = (const float*)d_in[5];
    const float* lam    = (const float*)d_in[6];
    const float* temp   = (const float*)d_in[7];

    float* alpha  = (float*)d_out;
    float* scores = alpha  + (size_t)Bn * Nn;
    float* keys   = scores + (size_t)Bn * Nn;

    __nv_bfloat16 *BhT, *BlT, *WQh, *WQl, *Qh, *Ql, *Kh, *Kl;
    float *qraw;
    cudaGetSymbolAddress((void**)&BhT,  g_BhT);
    cudaGetSymbolAddress((void**)&BlT,  g_BlT);
    cudaGetSymbolAddress((void**)&WQh,  g_WQh);
    cudaGetSymbolAddress((void**)&WQl,  g_WQl);
    cudaGetSymbolAddress((void**)&Qh,   g_Qh);
    cudaGetSymbolAddress((void**)&Ql,   g_Ql);
    cudaGetSymbolAddress((void**)&Kh,   g_Kh);
    cudaGetSymbolAddress((void**)&Kl,   g_Kl);
    cudaGetSymbolAddress((void**)&qraw, g_qraw);

    // Not a stream op; safe under graph capture; stateless per contract.
    cudaFuncSetAttribute(k_gemm01,
                         cudaFuncAttributeMaxDynamicSharedMemorySize, 98304);
    cudaFuncSetAttribute(k_gemm2,
                         cudaFuncAttributeMaxDynamicSharedMemorySize, 98304);

    // prep: single fused transpose+split launch for both weight tensors
    k_split_T2<<<dim3(Sn, DAn / 64 + Dn / 64), 256>>>(WQ, WQh, WQl, WK, BhT, BlT);

    // GEMM1 (keys) + GEMM0 (queries), CFG1, 2 CTAs/SM.
    k_gemm01<<<544, 256, 98304>>>(pool, z, BhT, BlT, WQh, WQl,
                                  keys, qraw, Kh, Kl, Qh, Ql, logits);

    // GEMM2: scores[512,8192] = Qt @ Khat^T
    k_gemm2<<<dim3(Nn / 128, Bn / 64), 256, 98304>>>(Qh, Ql, Kh, Kl, scores);

    k_alpha<<<Bn, 256>>>(scores, alpha, tau, lam, temp);
}

// round 15
// speedup vs baseline: 1.0853x; 1.0853x over previous
#include <cuda_runtime.h>
#include <cuda_bf16.h>
#include <cstdint>
#include <math.h>

// Problem constants
static constexpr int Bn  = 512;    // batch
static constexpr int Nn  = 8192;   // pool
static constexpr int Dn  = 1024;   // pool dim
static constexpr int DAn = 512;    // z dim
static constexpr int Sn  = 8;      // aspects
static constexpr int DKn = 64;     // head dim
static constexpr int Jn  = Sn * DKn; // 512 flattened key/query dim

// ---------------------------------------------------------------------------
// Scratch (device globals; no allocation allowed)
// ---------------------------------------------------------------------------
__device__ __nv_bfloat16 g_BhT[Jn * Dn];   // W_K^T hi  [512,1024]
__device__ __nv_bfloat16 g_BlT[Jn * Dn];   // W_K^T lo
__device__ __nv_bfloat16 g_WQh[Jn * DAn];  // W_Q^T hi  [512,512]
__device__ __nv_bfloat16 g_WQl[Jn * DAn];
__device__ __nv_bfloat16 g_Qh[Bn * Jn];    // weighted normalized queries hi
__device__ __nv_bfloat16 g_Ql[Bn * Jn];
__device__ __nv_bfloat16 g_Kh[Nn * Jn];    // normalized keys hi [8192,512]
__device__ __nv_bfloat16 g_Kl[Nn * Jn];
__device__ float         g_qraw[Bn * Jn];  // raw queries fp32 (discarded)

// ---------------------------------------------------------------------------
// helpers
// ---------------------------------------------------------------------------
__device__ __forceinline__ uint32_t smem_to_u32(const void* smem_ptr) {
    uint32_t addr;
    asm("{ .reg .u64 tmp; cvta.to.shared.u64 tmp, %1; cvt.u32.u64 %0, tmp; }"
        : "=r"(addr) : "l"(smem_ptr));
    return addr;
}

__device__ __forceinline__ void cp16(uint32_t dst, const void* src) {
    asm volatile("cp.async.cg.shared.global [%0], [%1], 16;"
                 :: "r"(dst), "l"(src) : "memory");
}
#define CP_COMMIT() asm volatile("cp.async.commit_group;" ::: "memory")
#define CP_WAIT(n)  asm volatile("cp.async.wait_group %0;" :: "n"(n) : "memory")

__device__ __forceinline__ void ldsm_x4(uint32_t* r, uint32_t addr) {
    asm volatile("ldmatrix.sync.aligned.m8n8.x4.shared.b16 {%0,%1,%2,%3}, [%4];"
                 : "=r"(r[0]), "=r"(r[1]), "=r"(r[2]), "=r"(r[3]) : "r"(addr));
}

__device__ __forceinline__ void mma_bf16(float* c, const uint32_t* a, const uint32_t* b) {
    asm volatile(
        "mma.sync.aligned.m16n8k16.row.col.f32.bf16.bf16.f32 "
        "{%0,%1,%2,%3}, {%4,%5,%6,%7}, {%8,%9}, {%0,%1,%2,%3};"
        : "+f"(c[0]), "+f"(c[1]), "+f"(c[2]), "+f"(c[3])
        : "r"(a[0]), "r"(a[1]), "r"(a[2]), "r"(a[3]), "r"(b[0]), "r"(b[1]));
}

__device__ __forceinline__ void sts64(uint32_t addr, uint32_t a, uint32_t b) {
    asm volatile("st.shared.v2.b32 [%0], {%1,%2};" :: "r"(addr), "r"(a), "r"(b) : "memory");
}

#define SWZ(off) ((off) ^ (((off) >> 3) & 0x70))

__device__ __forceinline__ void bf16_split(float v, __nv_bfloat16& h, __nv_bfloat16& l) {
    h = __float2bfloat16(v);
    l = __float2bfloat16(v - __bfloat162float(h));
}

// FMA-only reciprocal (frees the MUFU pipe): bit-trick seed + 3 Newton iters.
// Relative error ~1e-10 for normal positive inputs.
__device__ __forceinline__ float rcp_fma(float d) {
    float x = __uint_as_float(0x7EF311C3u - __float_as_uint(d));
    x = x * (2.f - d * x);
    x = x * (2.f - d * x);
    x = x * (2.f - d * x);
    return x;
}

// ---------------------------------------------------------------------------
// K0T2: fused transpose+split of BOTH weight tensors.
// grid (Sn, 24): y<8 -> W_Q (D=512) tile y ; y>=8 -> W_K (D=1024) tile y-8.
// ---------------------------------------------------------------------------
__global__ void __launch_bounds__(256) k_split_T2(
    const float* __restrict__ WQ, __nv_bfloat16* __restrict__ QH,
    __nv_bfloat16* __restrict__ QL,
    const float* __restrict__ WK, __nv_bfloat16* __restrict__ KH,
    __nv_bfloat16* __restrict__ KL)
{
    __shared__ float tile[64][65];
    int a  = blockIdx.x;
    int y  = blockIdx.y;
    const float* W; __nv_bfloat16 *H, *L; int D, p0;
    if (y < DAn / 64) { W = WQ; H = QH; L = QL; D = DAn; p0 = y * 64; }
    else              { W = WK; H = KH; L = KL; D = Dn;  p0 = (y - DAn / 64) * 64; }

    int t  = threadIdx.x;
    int q  = t & 63, rr = t >> 6;

    const float* src = W + (size_t)a * (D * DKn) + (size_t)p0 * DKn;
#pragma unroll
    for (int pi = rr; pi < 64; pi += 4)
        tile[pi][q] = src[pi * DKn + q];
    __syncthreads();

    int pi = t & 63, qb = t >> 6;
#pragma unroll
    for (int qq = qb; qq < 64; qq += 4) {
        float v = tile[pi][qq];
        __nv_bfloat16 h, l;
        bf16_split(v, h, l);
        size_t off = (size_t)(a * 64 + qq) * D + p0 + pi;
        H[off] = h;
        L[off] = l;
    }
}

// ---------------------------------------------------------------------------
// Split-3 bf16 GEMM body on mma.sync (proven R13 config, CFG0):
//   C[M,N] = Ah*Bh^T + Al*Bh^T + Ah*Bl^T
// CFG=0: 128x256 tile, 512 thr (16 warps 4m x 4n), warp 32x64. 192KB smem.
// BK=64, 2-stage cp.async double buffer, SW128 swizzle.
// CVT_A:  A read as fp32, split to bf16 hi/lo in-kernel.
// FUSE_NORM: L2-normalize each row's 64-wide aspect block (== warpN block);
//         Wv (if non-null) = RAW aspect logits, softmax inline.
// ---------------------------------------------------------------------------
template <int CFG, bool FUSE_NORM, bool CVT_A>
__device__ __forceinline__ void gemm_body(
    const float* __restrict__ A32,
    const __nv_bfloat16* __restrict__ Ah, const __nv_bfloat16* __restrict__ Al,
    const __nv_bfloat16* __restrict__ Bh, const __nv_bfloat16* __restrict__ Bl,
    float* __restrict__ C, int Ktot, int ldC,
    __nv_bfloat16* __restrict__ Kh, __nv_bfloat16* __restrict__ Kl,
    const float* __restrict__ Wv,
    int m0, int n0, uint8_t* smem)
{
    constexpr int THREADS = CFG == 0 ? 512 : (CFG == 1 ? 256 : 128);
    constexpr int MI      = CFG == 0 ? 2 : 1;
    constexpr int M_TILE  = CFG == 0 ? 128 : 64;
    constexpr int N_TILE  = CFG == 0 ? 256 : (CFG == 1 ? 128 : 64);
    constexpr uint32_t AT     = M_TILE * 128;
    constexpr uint32_t BT     = N_TILE * 128;
    constexpr uint32_t OFF_AL = AT;
    constexpr uint32_t OFF_BH = 2 * AT;
    constexpr uint32_t OFF_BL = 2 * AT + BT;
    constexpr uint32_t STAGE  = 2 * AT + 2 * BT;

    const int t    = threadIdx.x;
    const int lane = t & 31;
    const int wid  = t >> 5;
    const int warpM = wid & 3;
    const int warpN = wid >> 2;

    const uint32_t smem_u = smem_to_u32(smem);

    auto loadB = [&](int kt, int s) {
        uint32_t base = smem_u + (uint32_t)s * STAGE;
        int koff = kt * 64;
#pragma unroll
        for (int i = 0; i < (N_TILE * 8) / THREADS; i++) {
            int c   = t + i * THREADS;
            int row = c >> 3, grp = c & 7;
            uint32_t soff = SWZ((uint32_t)(row * 128 + grp * 16));
            size_t boff = (size_t)(n0 + row) * Ktot + koff + grp * 8;
            cp16(base + OFF_BH + soff, Bh + boff);
            cp16(base + OFF_BL + soff, Bl + boff);
        }
    };

    auto loadA_bf16 = [&](int kt, int s) {
        uint32_t base = smem_u + (uint32_t)s * STAGE;
        int koff = kt * 64;
#pragma unroll
        for (int i = 0; i < (M_TILE * 8) / THREADS; i++) {
            int c   = t + i * THREADS;
            int row = c >> 3, grp = c & 7;
            uint32_t soff = SWZ((uint32_t)(row * 128 + grp * 16));
            size_t aoff = (size_t)(m0 + row) * Ktot + koff + grp * 8;
            cp16(base + soff,          Ah + aoff);
            cp16(base + OFF_AL + soff, Al + aoff);
        }
    };

    constexpr int NAV = (M_TILE * 16) / THREADS;
    float4 av[NAV];
    auto ldgA = [&](int kt) {
#pragma unroll
        for (int i = 0; i < NAV; i++) {
            int c = t + i * THREADS;
            int row = c >> 4, f4 = c & 15;
            av[i] = *(const float4*)(A32 + (size_t)(m0 + row) * Ktot + kt * 64 + f4 * 4);
        }
    };
    auto cvtstsA = [&](int s) {
        uint32_t base = smem_u + (uint32_t)s * STAGE;
#pragma unroll
        for (int i = 0; i < NAV; i++) {
            int c = t + i * THREADS;
            int row = c >> 4, f4 = c & 15;
            uint32_t so = SWZ((uint32_t)(row * 128 + f4 * 8));
            __nv_bfloat16 h0,l0,h1,l1,h2,l2,h3,l3;
            bf16_split(av[i].x, h0, l0); bf16_split(av[i].y, h1, l1);
            bf16_split(av[i].z, h2, l2); bf16_split(av[i].w, h3, l3);
            __nv_bfloat162 pA, pB;
            pA.x = h0; pA.y = h1; pB.x = h2; pB.y = h3;
            uint32_t hx = *(uint32_t*)&pA, hy = *(uint32_t*)&pB;
            pA.x = l0; pA.y = l1; pB.x = l2; pB.y = l3;
            uint32_t lx = *(uint32_t*)&pA, ly = *(uint32_t*)&pB;
            sts64(base + so,          hx, hy);
            sts64(base + OFF_AL + so, lx, ly);
        }
    };

    const int arow  = warpM * (16 * MI) + (lane & 15);
    const int acolg = (lane >> 4) * 16;
    const int bg    = lane >> 3;
    const int brow  = warpN * 64 + ((bg >= 2) ? 8 : 0) + (lane & 7);
    const int bcol  = (bg & 1) * 16;

    float acc[MI][8][4];
#pragma unroll
    for (int mi = 0; mi < MI; mi++)
#pragma unroll
        for (int nj = 0; nj < 8; nj++)
#pragma unroll
            for (int r = 0; r < 4; r++) acc[mi][nj][r] = 0.f;

    const int KT = Ktot >> 6;

    if (CVT_A) {
        ldgA(0);
        cvtstsA(0);
        loadB(0, 0);
    } else {
        loadA_bf16(0, 0);
        loadB(0, 0);
    }
    CP_COMMIT();

    for (int kt = 0; kt < KT; kt++) {
        if (kt + 1 < KT) {
            if (CVT_A) {
                ldgA(kt + 1);
                loadB(kt + 1, (kt + 1) & 1);
            } else {
                loadA_bf16(kt + 1, (kt + 1) & 1);
                loadB(kt + 1, (kt + 1) & 1);
            }
            CP_COMMIT();
            CP_WAIT(1);
        } else {
            CP_WAIT(0);
        }
        __syncthreads();

        uint32_t base = smem_u + (uint32_t)(kt & 1) * STAGE;

#pragma unroll
        for (int ks = 0; ks < 4; ks++) {
            uint32_t ah[MI][4], al[MI][4];
#pragma unroll
            for (int mi = 0; mi < MI; mi++) {
                uint32_t off = SWZ((uint32_t)((arow + mi * 16) * 128 + ks * 32 + acolg));
                ldsm_x4(ah[mi], base + off);
                ldsm_x4(al[mi], base + OFF_AL + off);
            }
#pragma unroll
            for (int njp = 0; njp < 4; njp++) {
                uint32_t bh[4], bl[4];
                uint32_t off = SWZ((uint32_t)((brow + njp * 16) * 128 + ks * 32 + bcol));
                ldsm_x4(bh, base + OFF_BH + off);
                ldsm_x4(bl, base + OFF_BL + off);
#pragma unroll
                for (int half = 0; half < 2; half++) {
                    int nj = njp * 2 + half;
                    const uint32_t* bhf = &bh[half * 2];
                    const uint32_t* blf = &bl[half * 2];
#pragma unroll
                    for (int mi = 0; mi < MI; mi++) {
                        mma_bf16(acc[mi][nj], ah[mi], bhf);
                        mma_bf16(acc[mi][nj], al[mi], bhf);
                        mma_bf16(acc[mi][nj], ah[mi], blf);
                    }
                }
            }
        }

        if (CVT_A && kt + 1 < KT) cvtstsA((kt + 1) & 1);
        __syncthreads();
    }

    // --- epilogue ---
    float wa = 1.f;
    if (FUSE_NORM && Wv != nullptr) {
        int aspect = (n0 + warpN * 64) >> 6;
        float m = Wv[0];
#pragma unroll
        for (int i = 1; i < Sn; i++) m = fmaxf(m, Wv[i]);
        float s = 0.f, ea = 0.f;
#pragma unroll
        for (int i = 0; i < Sn; i++) {
            float e = __expf(Wv[i] - m);
            s += e;
            if (i == aspect) ea = e;
        }
        wa = ea / s;
    }

#pragma unroll
    for (int mi = 0; mi < MI; mi++) {
        int r0 = m0 + warpM * (16 * MI) + mi * 16 + (lane >> 2);
        int r1 = r0 + 8;
        int colb = n0 + warpN * 64 + (lane & 3) * 2;

        float inv0 = 1.f, inv1 = 1.f;
        if (FUSE_NORM) {
            float s0 = 0.f, s1 = 0.f;
#pragma unroll
            for (int nj = 0; nj < 8; nj++) {
                s0 = fmaf(acc[mi][nj][0], acc[mi][nj][0], s0);
                s0 = fmaf(acc[mi][nj][1], acc[mi][nj][1], s0);
                s1 = fmaf(acc[mi][nj][2], acc[mi][nj][2], s1);
                s1 = fmaf(acc[mi][nj][3], acc[mi][nj][3], s1);
            }
            s0 += __shfl_xor_sync(0xffffffffu, s0, 1);
            s0 += __shfl_xor_sync(0xffffffffu, s0, 2);
            s1 += __shfl_xor_sync(0xffffffffu, s1, 1);
            s1 += __shfl_xor_sync(0xffffffffu, s1, 2);
            inv0 = wa / (sqrtf(s0) + 1e-8f);
            inv1 = wa / (sqrtf(s1) + 1e-8f);
        }

#pragma unroll
        for (int nj = 0; nj < 8; nj++) {
            int col = colb + nj * 8;
            *(float2*)&C[(size_t)r0 * ldC + col] = make_float2(acc[mi][nj][0], acc[mi][nj][1]);
            *(float2*)&C[(size_t)r1 * ldC + col] = make_float2(acc[mi][nj][2], acc[mi][nj][3]);
            if (FUSE_NORM) {
                __nv_bfloat16 h0, l0, h1, l1;
                __nv_bfloat162 hh, ll;
                bf16_split(acc[mi][nj][0] * inv0, h0, l0);
                bf16_split(acc[mi][nj][1] * inv0, h1, l1);
                hh.x = h0; hh.y = h1; ll.x = l0; ll.y = l1;
                *(__nv_bfloat162*)&Kh[(size_t)r0 * ldC + col] = hh;
                *(__nv_bfloat162*)&Kl[(size_t)r0 * ldC + col] = ll;
                bf16_split(acc[mi][nj][2] * inv1, h0, l0);
                bf16_split(acc[mi][nj][3] * inv1, h1, l1);
                hh.x = h0; hh.y = h1; ll.x = l0; ll.y = l1;
                *(__nv_bfloat162*)&Kh[(size_t)r1 * ldC + col] = hh;
                *(__nv_bfloat162*)&Kl[(size_t)r1 * ldC + col] = ll;
            }
        }
    }
}

// ---------------------------------------------------------------------------
// Fused GEMM1 + GEMM0 launch (both CFG0/FUSE_NORM/CVT_A; one wave of 136):
//   blocks [0,128):   GEMM1 keys  = pool @ WkT^T   (2 n-tiles x 64 m-tiles)
//   blocks [128,136): GEMM0 query = z    @ WQT^T   (2 n-tiles x  4 m-tiles)
// GEMM0 blocks run in the shadow of GEMM1 on the otherwise-idle SMs.
// ---------------------------------------------------------------------------
__global__ void __launch_bounds__(512) k_gemm01(
    const float* __restrict__ pool, const float* __restrict__ z,
    const __nv_bfloat16* __restrict__ BhT, const __nv_bfloat16* __restrict__ BlT,
    const __nv_bfloat16* __restrict__ WQh, const __nv_bfloat16* __restrict__ WQl,
    float* __restrict__ keys, float* __restrict__ qraw,
    __nv_bfloat16* __restrict__ Kh, __nv_bfloat16* __restrict__ Kl,
    __nv_bfloat16* __restrict__ Qh, __nv_bfloat16* __restrict__ Ql,
    const float* __restrict__ logits)
{
    extern __shared__ __align__(1024) uint8_t smem[];
    int b = blockIdx.x;
    const float* A32; const __nv_bfloat16 *Bh, *Bl; float* C;
    __nv_bfloat16 *KH, *KL; const float* Wv;
    int Ktot, m0, n0;
    if (b < 128) {          // GEMM1
        A32 = pool; Bh = BhT; Bl = BlT; C = keys; KH = Kh; KL = Kl;
        Wv = nullptr; Ktot = Dn;
        n0 = (b & 1) * 256; m0 = (b >> 1) * 128;
    } else {                // GEMM0
        int b2 = b - 128;
        A32 = z; Bh = WQh; Bl = WQl; C = qraw; KH = Qh; KL = Ql;
        Wv = logits; Ktot = DAn;
        n0 = (b2 & 1) * 256; m0 = (b2 >> 1) * 128;
    }
    gemm_body<0, true, true>(A32, nullptr, nullptr, Bh, Bl, C, Ktot, Jn,
                             KH, KL, Wv, m0, n0, smem);
}

// ---------------------------------------------------------------------------
// GEMM2: scores = Qt @ Khat^T (bf16 operands, cp.async path). grid (32,4).
// ---------------------------------------------------------------------------
__global__ void __launch_bounds__(512) k_gemm2(
    const __nv_bfloat16* __restrict__ Qh, const __nv_bfloat16* __restrict__ Ql,
    const __nv_bfloat16* __restrict__ Kh, const __nv_bfloat16* __restrict__ Kl,
    float* __restrict__ scores)
{
    extern __shared__ __align__(1024) uint8_t smem[];
    int m0 = blockIdx.y * 128;
    int n0 = blockIdx.x * 256;
    gemm_body<0, false, false>(nullptr, Qh, Ql, Kh, Kl, scores, Jn, Nn,
                               nullptr, nullptr, nullptr, m0, n0, smem);
}

// ---------------------------------------------------------------------------
// K5: gate + temperature-scaled normalize -> alpha. One block per batch row.
// 512 threads (occ: warps/SM ~56 to feed MUFU); FMA-reciprocal replaces the
// per-element division (2 MUFU + FMAs per element instead of 3 MUFU).
// Register-resident: 4 float4 per thread.
// ---------------------------------------------------------------------------
__global__ void __launch_bounds__(512) k_alpha(
    const float* __restrict__ scores, float* __restrict__ alpha,
    const float* __restrict__ ptau, const float* __restrict__ plam,
    const float* __restrict__ ptemp)
{
    __shared__ float red[16];
    __shared__ float stot;

    int t = threadIdx.x, b = blockIdx.x;
    float tau = *ptau, lam = *plam, invT = 1.f / (*ptemp);

    float4 rv[4];
    float s_local = 0.f;
    const float4* src = (const float4*)(scores + (size_t)b * Nn);
#pragma unroll
    for (int i = 0; i < 4; i++) {
        float4 s4 = src[t + i * 512];
        rv[i].x = __expf(s4.x * invT) * rcp_fma(1.f + __expf(-lam * (s4.x - tau)));
        rv[i].y = __expf(s4.y * invT) * rcp_fma(1.f + __expf(-lam * (s4.y - tau)));
        rv[i].z = __expf(s4.z * invT) * rcp_fma(1.f + __expf(-lam * (s4.z - tau)));
        rv[i].w = __expf(s4.w * invT) * rcp_fma(1.f + __expf(-lam * (s4.w - tau)));
        s_local += (rv[i].x + rv[i].y) + (rv[i].z + rv[i].w);
    }
#pragma unroll
    for (int off = 16; off > 0; off >>= 1)
        s_local += __shfl_xor_sync(0xffffffffu, s_local, off);
    if ((t & 31) == 0) red[t >> 5] = s_local;
    __syncthreads();
    if (t == 0) {
        float s = 0.f;
        for (int w = 0; w < 16; w++) s += red[w];
        stot = s;
    }
    __syncthreads();

    float inv = 1.f / (stot + 1e-8f);
    float4* dst = (float4*)(alpha + (size_t)b * Nn);
#pragma unroll
    for (int i = 0; i < 4; i++)
        dst[t + i * 512] = make_float4(rv[i].x * inv, rv[i].y * inv,
                                       rv[i].z * inv, rv[i].w * inv);
}

// ---------------------------------------------------------------------------
extern "C" void kernel_launch(void* const* d_in, const int* in_sizes, int n_in,
                              void* d_out, int out_size)
{
    const float* z      = (const float*)d_in[0];
    const float* pool   = (const float*)d_in[1];
    const float* WQ     = (const float*)d_in[2];
    const float* WK     = (const float*)d_in[3];
    const float* logits = (const float*)d_in[4];
    const float* tau    = (const float*)d_in[5];
    const float* lam    = (const float*)d_in[6];
    const float* temp   = (const float*)d_in[7];

    float* alpha  = (float*)d_out;
    float* scores = alpha  + (size_t)Bn * Nn;
    float* keys   = scores + (size_t)Bn * Nn;

    __nv_bfloat16 *BhT, *BlT, *WQh, *WQl, *Qh, *Ql, *Kh, *Kl;
    float *qraw;
    cudaGetSymbolAddress((void**)&BhT,  g_BhT);
    cudaGetSymbolAddress((void**)&BlT,  g_BlT);
    cudaGetSymbolAddress((void**)&WQh,  g_WQh);
    cudaGetSymbolAddress((void**)&WQl,  g_WQl);
    cudaGetSymbolAddress((void**)&Qh,   g_Qh);
    cudaGetSymbolAddress((void**)&Ql,   g_Ql);
    cudaGetSymbolAddress((void**)&Kh,   g_Kh);
    cudaGetSymbolAddress((void**)&Kl,   g_Kl);
    cudaGetSymbolAddress((void**)&qraw, g_qraw);

    // Not a stream op; safe under graph capture; stateless per contract.
    cudaFuncSetAttribute(k_gemm01,
                         cudaFuncAttributeMaxDynamicSharedMemorySize, 196608);
    cudaFuncSetAttribute(k_gemm2,
                         cudaFuncAttributeMaxDynamicSharedMemorySize, 196608);

    // prep: single fused transpose+split launch for both weight tensors
    k_split_T2<<<dim3(Sn, DAn / 64 + Dn / 64), 256>>>(WQ, WQh, WQl, WK, BhT, BlT);

    // GEMM1 (keys) + GEMM0 (queries) fused into one 136-block wave.
    k_gemm01<<<136, 512, 196608>>>(pool, z, BhT, BlT, WQh, WQl,
                                   keys, qraw, Kh, Kl, Qh, Ql, logits);

    // GEMM2: scores[512,8192] = Qt @ Khat^T
    k_gemm2<<<dim3(Nn / 256, Bn / 128), 512, 196608>>>(Qh, Ql, Kh, Kl, scores);

    k_alpha<<<Bn, 512>>>(scores, alpha, tau, lam, temp);
}

// round 17
// speedup vs baseline: 1.4738x; 1.3579x over previous
#include <cuda_runtime.h>
#include <cuda_fp16.h>
#include <cstdint>
#include <math.h>

// Problem constants
static constexpr int Bn  = 512;    // batch
static constexpr int Nn  = 8192;   // pool
static constexpr int Dn  = 1024;   // pool dim
static constexpr int DAn = 512;    // z dim
static constexpr int Sn  = 8;      // aspects
static constexpr int DKn = 64;     // head dim
static constexpr int Jn  = Sn * DKn; // 512 flattened key/query dim

// ---------------------------------------------------------------------------
// Scratch (device globals; no allocation allowed)
// fp16 operands: B-side single precision (2^-12), A-side hi/lo split.
// ---------------------------------------------------------------------------
__device__ __half g_BhT[Jn * Dn];    // W_K^T fp16 [512,1024]
__device__ __half g_WQh[Jn * DAn];   // W_Q^T fp16 [512,512]
__device__ __half g_Qh[Bn * Jn];     // weighted normalized queries hi
__device__ __half g_Ql[Bn * Jn];     // lo (A-side split for GEMM2)
__device__ __half g_Kh[Nn * Jn];     // normalized keys fp16 [8192,512]
__device__ float  g_qraw[Bn * Jn];   // raw queries fp32 (discarded)

// ---------------------------------------------------------------------------
// helpers
// ---------------------------------------------------------------------------
__device__ __forceinline__ uint32_t smem_to_u32(const void* smem_ptr) {
    uint32_t addr;
    asm("{ .reg .u64 tmp; cvta.to.shared.u64 tmp, %1; cvt.u32.u64 %0, tmp; }"
        : "=r"(addr) : "l"(smem_ptr));
    return addr;
}

__device__ __forceinline__ void cp16(uint32_t dst, const void* src) {
    asm volatile("cp.async.cg.shared.global [%0], [%1], 16;"
                 :: "r"(dst), "l"(src) : "memory");
}
#define CP_COMMIT() asm volatile("cp.async.commit_group;" ::: "memory")
#define CP_WAIT(n)  asm volatile("cp.async.wait_group %0;" :: "n"(n) : "memory")

__device__ __forceinline__ void ldsm_x4(uint32_t* r, uint32_t addr) {
    asm volatile("ldmatrix.sync.aligned.m8n8.x4.shared.b16 {%0,%1,%2,%3}, [%4];"
                 : "=r"(r[0]), "=r"(r[1]), "=r"(r[2]), "=r"(r[3]) : "r"(addr));
}

__device__ __forceinline__ void mma_f16(float* c, const uint32_t* a, const uint32_t* b) {
    asm volatile(
        "mma.sync.aligned.m16n8k16.row.col.f32.f16.f16.f32 "
        "{%0,%1,%2,%3}, {%4,%5,%6,%7}, {%8,%9}, {%0,%1,%2,%3};"
        : "+f"(c[0]), "+f"(c[1]), "+f"(c[2]), "+f"(c[3])
        : "r"(a[0]), "r"(a[1]), "r"(a[2]), "r"(a[3]), "r"(b[0]), "r"(b[1]));
}

__device__ __forceinline__ void sts64(uint32_t addr, uint32_t a, uint32_t b) {
    asm volatile("st.shared.v2.b32 [%0], {%1,%2};" :: "r"(addr), "r"(a), "r"(b) : "memory");
}

#define SWZ(off) ((off) ^ (((off) >> 3) & 0x70))

__device__ __forceinline__ void h16_split(float v, __half& h, __half& l) {
    h = __float2half_rn(v);
    l = __float2half_rn(v - __half2float(h));
}

// FMA-only reciprocal (frees the MUFU pipe): bit-trick seed + 3 Newton iters.
__device__ __forceinline__ float rcp_fma(float d) {
    float x = __uint_as_float(0x7EF311C3u - __float_as_uint(d));
    x = x * (2.f - d * x);
    x = x * (2.f - d * x);
    x = x * (2.f - d * x);
    return x;
}

// ---------------------------------------------------------------------------
// K0T2: fused transpose of BOTH weight tensors to fp16 (single precision).
// grid (Sn, 24): y<8 -> W_Q (D=512) tile y ; y>=8 -> W_K (D=1024) tile y-8.
// ---------------------------------------------------------------------------
__global__ void __launch_bounds__(256) k_split_T2(
    const float* __restrict__ WQ, __half* __restrict__ QH,
    const float* __restrict__ WK, __half* __restrict__ KH)
{
    __shared__ float tile[64][65];
    int a  = blockIdx.x;
    int y  = blockIdx.y;
    const float* W; __half* H; int D, p0;
    if (y < DAn / 64) { W = WQ; H = QH; D = DAn; p0 = y * 64; }
    else              { W = WK; H = KH; D = Dn;  p0 = (y - DAn / 64) * 64; }

    int t  = threadIdx.x;
    int q  = t & 63, rr = t >> 6;

    const float* src = W + (size_t)a * (D * DKn) + (size_t)p0 * DKn;
#pragma unroll
    for (int pi = rr; pi < 64; pi += 4)
        tile[pi][q] = src[pi * DKn + q];
    __syncthreads();

    int pi = t & 63, qb = t >> 6;
#pragma unroll
    for (int qq = qb; qq < 64; qq += 4) {
        size_t off = (size_t)(a * 64 + qq) * D + p0 + pi;
        H[off] = __float2half_rn(tile[pi][qq]);
    }
}

// ---------------------------------------------------------------------------
// Split-2 fp16 GEMM body on mma.sync:
//   C[M,N] = Ah*Bh^T + Al*Bh^T      (A split-2 fp16, B single fp16)
// CFG=0: 128x256 tile, 512 thr (16 warps 4m x 4n), warp 32x64.
// Stage: Ah 16K | Al 16K | Bh 32K = 64KB; 2 stages = 128KB smem.
// BK=64, 2-stage cp.async double buffer, SW128 swizzle.
// CVT_A:  A read as fp32, split to fp16 hi/lo in-kernel (LDG early, STS after
//         compute — DRAM latency hidden under the MMA block).
// FUSE_NORM: L2-normalize each row's 64-wide aspect block (== warpN block);
//         Wv (if non-null) = RAW aspect logits, softmax inline.
//         Writes fp16 Kh (and Kl if non-null: A-side split for next GEMM).
// ---------------------------------------------------------------------------
template <bool FUSE_NORM, bool CVT_A>
__device__ __forceinline__ void gemm_body(
    const float* __restrict__ A32,
    const __half* __restrict__ Ah, const __half* __restrict__ Al,
    const __half* __restrict__ Bh,
    float* __restrict__ C, int Ktot, int ldC,
    __half* __restrict__ Kh, __half* __restrict__ Kl,
    const float* __restrict__ Wv,
    int m0, int n0, uint8_t* smem)
{
    constexpr int THREADS = 512;
    constexpr int MI      = 2;
    constexpr int M_TILE  = 128;
    constexpr int N_TILE  = 256;
    constexpr uint32_t AT     = M_TILE * 128;   // 16 KB per A tile (h or l)
    constexpr uint32_t BT     = N_TILE * 128;   // 32 KB Bh tile
    constexpr uint32_t OFF_AL = AT;
    constexpr uint32_t OFF_BH = 2 * AT;
    constexpr uint32_t STAGE  = 2 * AT + BT;    // 64 KB

    const int t    = threadIdx.x;
    const int lane = t & 31;
    const int wid  = t >> 5;
    const int warpM = wid & 3;
    const int warpN = wid >> 2;

    const uint32_t smem_u = smem_to_u32(smem);

    auto loadB = [&](int kt, int s) {
        uint32_t base = smem_u + (uint32_t)s * STAGE;
        int koff = kt * 64;
#pragma unroll
        for (int i = 0; i < (N_TILE * 8) / THREADS; i++) {   // 4 iters
            int c   = t + i * THREADS;
            int row = c >> 3, grp = c & 7;
            uint32_t soff = SWZ((uint32_t)(row * 128 + grp * 16));
            size_t boff = (size_t)(n0 + row) * Ktot + koff + grp * 8;
            cp16(base + OFF_BH + soff, Bh + boff);
        }
    };

    auto loadA_f16 = [&](int kt, int s) {
        uint32_t base = smem_u + (uint32_t)s * STAGE;
        int koff = kt * 64;
#pragma unroll
        for (int i = 0; i < (M_TILE * 8) / THREADS; i++) {   // 2 iters
            int c   = t + i * THREADS;
            int row = c >> 3, grp = c & 7;
            uint32_t soff = SWZ((uint32_t)(row * 128 + grp * 16));
            size_t aoff = (size_t)(m0 + row) * Ktot + koff + grp * 8;
            cp16(base + soff,          Ah + aoff);
            cp16(base + OFF_AL + soff, Al + aoff);
        }
    };

    constexpr int NAV = (M_TILE * 16) / THREADS;  // 4 float4 per thread
    float4 av[NAV];
    auto ldgA = [&](int kt) {
#pragma unroll
        for (int i = 0; i < NAV; i++) {
            int c = t + i * THREADS;
            int row = c >> 4, f4 = c & 15;
            av[i] = *(const float4*)(A32 + (size_t)(m0 + row) * Ktot + kt * 64 + f4 * 4);
        }
    };
    auto cvtstsA = [&](int s) {
        uint32_t base = smem_u + (uint32_t)s * STAGE;
#pragma unroll
        for (int i = 0; i < NAV; i++) {
            int c = t + i * THREADS;
            int row = c >> 4, f4 = c & 15;
            uint32_t so = SWZ((uint32_t)(row * 128 + f4 * 8));
            __half h0,l0,h1,l1,h2,l2,h3,l3;
            h16_split(av[i].x, h0, l0); h16_split(av[i].y, h1, l1);
            h16_split(av[i].z, h2, l2); h16_split(av[i].w, h3, l3);
            __half2 pA, pB;
            pA.x = h0; pA.y = h1; pB.x = h2; pB.y = h3;
            uint32_t hx = *(uint32_t*)&pA, hy = *(uint32_t*)&pB;
            pA.x = l0; pA.y = l1; pB.x = l2; pB.y = l3;
            uint32_t lx = *(uint32_t*)&pA, ly = *(uint32_t*)&pB;
            sts64(base + so,          hx, hy);
            sts64(base + OFF_AL + so, lx, ly);
        }
    };

    const int arow  = warpM * 32 + (lane & 15);
    const int acolg = (lane >> 4) * 16;
    const int bg    = lane >> 3;
    const int brow  = warpN * 64 + ((bg >= 2) ? 8 : 0) + (lane & 7);
    const int bcol  = (bg & 1) * 16;

    float acc[MI][8][4];
#pragma unroll
    for (int mi = 0; mi < MI; mi++)
#pragma unroll
        for (int nj = 0; nj < 8; nj++)
#pragma unroll
            for (int r = 0; r < 4; r++) acc[mi][nj][r] = 0.f;

    const int KT = Ktot >> 6;

    if (CVT_A) {
        ldgA(0);
        cvtstsA(0);
        loadB(0, 0);
    } else {
        loadA_f16(0, 0);
        loadB(0, 0);
    }
    CP_COMMIT();

    for (int kt = 0; kt < KT; kt++) {
        if (kt + 1 < KT) {
            if (CVT_A) {
                ldgA(kt + 1);                       // early issue; consumed post-compute
                loadB(kt + 1, (kt + 1) & 1);
            } else {
                loadA_f16(kt + 1, (kt + 1) & 1);
                loadB(kt + 1, (kt + 1) & 1);
            }
            CP_COMMIT();
            CP_WAIT(1);
        } else {
            CP_WAIT(0);
        }
        __syncthreads();        // stage kt fully visible; all warps past compute kt-1

        uint32_t base = smem_u + (uint32_t)(kt & 1) * STAGE;

#pragma unroll
        for (int ks = 0; ks < 4; ks++) {
            uint32_t ah[MI][4], al[MI][4];
#pragma unroll
            for (int mi = 0; mi < MI; mi++) {
                uint32_t off = SWZ((uint32_t)((arow + mi * 16) * 128 + ks * 32 + acolg));
                ldsm_x4(ah[mi], base + off);
                ldsm_x4(al[mi], base + OFF_AL + off);
            }
#pragma unroll
            for (int njp = 0; njp < 4; njp++) {
                uint32_t bh[4];
                uint32_t off = SWZ((uint32_t)((brow + njp * 16) * 128 + ks * 32 + bcol));
                ldsm_x4(bh, base + OFF_BH + off);
#pragma unroll
                for (int half = 0; half < 2; half++) {
                    int nj = njp * 2 + half;
                    const uint32_t* bhf = &bh[half * 2];
#pragma unroll
                    for (int mi = 0; mi < MI; mi++) {
                        mma_f16(acc[mi][nj], ah[mi], bhf);
                        mma_f16(acc[mi][nj], al[mi], bhf);
                    }
                }
            }
        }

        if (CVT_A && kt + 1 < KT) cvtstsA((kt + 1) & 1);   // LDG latency hidden by MMAs
        __syncthreads();        // all warps done reading stage kt before overwrite
    }

    // --- epilogue ---
    float wa = 1.f;
    if (FUSE_NORM && Wv != nullptr) {
        int aspect = (n0 + warpN * 64) >> 6;
        float m = Wv[0];
#pragma unroll
        for (int i = 1; i < Sn; i++) m = fmaxf(m, Wv[i]);
        float s = 0.f, ea = 0.f;
#pragma unroll
        for (int i = 0; i < Sn; i++) {
            float e = __expf(Wv[i] - m);
            s += e;
            if (i == aspect) ea = e;
        }
        wa = ea / s;
    }

#pragma unroll
    for (int mi = 0; mi < MI; mi++) {
        int r0 = m0 + warpM * 32 + mi * 16 + (lane >> 2);
        int r1 = r0 + 8;
        int colb = n0 + warpN * 64 + (lane & 3) * 2;

        float inv0 = 1.f, inv1 = 1.f;
        if (FUSE_NORM) {
            float s0 = 0.f, s1 = 0.f;
#pragma unroll
            for (int nj = 0; nj < 8; nj++) {
                s0 = fmaf(acc[mi][nj][0], acc[mi][nj][0], s0);
                s0 = fmaf(acc[mi][nj][1], acc[mi][nj][1], s0);
                s1 = fmaf(acc[mi][nj][2], acc[mi][nj][2], s1);
                s1 = fmaf(acc[mi][nj][3], acc[mi][nj][3], s1);
            }
            s0 += __shfl_xor_sync(0xffffffffu, s0, 1);
            s0 += __shfl_xor_sync(0xffffffffu, s0, 2);
            s1 += __shfl_xor_sync(0xffffffffu, s1, 1);
            s1 += __shfl_xor_sync(0xffffffffu, s1, 2);
            inv0 = wa / (sqrtf(s0) + 1e-8f);
            inv1 = wa / (sqrtf(s1) + 1e-8f);
        }

#pragma unroll
        for (int nj = 0; nj < 8; nj++) {
            int col = colb + nj * 8;
            *(float2*)&C[(size_t)r0 * ldC + col] = make_float2(acc[mi][nj][0], acc[mi][nj][1]);
            *(float2*)&C[(size_t)r1 * ldC + col] = make_float2(acc[mi][nj][2], acc[mi][nj][3]);
            if (FUSE_NORM) {
                __half h0, l0, h1, l1;
                __half2 hh, ll;
                h16_split(acc[mi][nj][0] * inv0, h0, l0);
                h16_split(acc[mi][nj][1] * inv0, h1, l1);
                hh.x = h0; hh.y = h1;
                *(__half2*)&Kh[(size_t)r0 * ldC + col] = hh;
                if (Kl) { ll.x = l0; ll.y = l1; *(__half2*)&Kl[(size_t)r0 * ldC + col] = ll; }
                h16_split(acc[mi][nj][2] * inv1, h0, l0);
                h16_split(acc[mi][nj][3] * inv1, h1, l1);
                hh.x = h0; hh.y = h1;
                *(__half2*)&Kh[(size_t)r1 * ldC + col] = hh;
                if (Kl) { ll.x = l0; ll.y = l1; *(__half2*)&Kl[(size_t)r1 * ldC + col] = ll; }
            }
        }
    }
}

// ---------------------------------------------------------------------------
// Fused GEMM1 + GEMM0 launch (one wave of 136 blocks, 512 thr, 128KB smem):
//   blocks [0,128):   GEMM1 keys  = pool @ WkT^T  -> keys fp32, Kh fp16
//   blocks [128,136): GEMM0 query = z    @ WQT^T  -> Qh+Ql fp16 (A-split)
// ---------------------------------------------------------------------------
__global__ void __launch_bounds__(512) k_gemm01(
    const float* __restrict__ pool, const float* __restrict__ z,
    const __half* __restrict__ BhT, const __half* __restrict__ WQh,
    float* __restrict__ keys, float* __restrict__ qraw,
    __half* __restrict__ Kh, __half* __restrict__ Qh, __half* __restrict__ Ql,
    const float* __restrict__ logits)
{
    extern __shared__ __align__(1024) uint8_t smem[];
    int b = blockIdx.x;
    if (b < 128) {          // GEMM1
        int n0 = (b & 1) * 256, m0 = (b >> 1) * 128;
        gemm_body<true, true>(pool, nullptr, nullptr, BhT, keys, Dn, Jn,
                              Kh, nullptr, nullptr, m0, n0, smem);
    } else {                // GEMM0
        int b2 = b - 128;
        int n0 = (b2 & 1) * 256, m0 = (b2 >> 1) * 128;
        gemm_body<true, true>(z, nullptr, nullptr, WQh, qraw, DAn, Jn,
                              Qh, Ql, logits, m0, n0, smem);
    }
}

// ---------------------------------------------------------------------------
// GEMM2: scores = (Qh+Ql) @ Kh^T (A split-2 fp16, B single fp16). grid (32,4).
// ---------------------------------------------------------------------------
__global__ void __launch_bounds__(512) k_gemm2(
    const __half* __restrict__ Qh, const __half* __restrict__ Ql,
    const __half* __restrict__ Kh, float* __restrict__ scores)
{
    extern __shared__ __align__(1024) uint8_t smem[];
    int m0 = blockIdx.y * 128;
    int n0 = blockIdx.x * 256;
    gemm_body<false, false>(nullptr, Qh, Ql, Kh, scores, Jn, Nn,
                            nullptr, nullptr, nullptr, m0, n0, smem);
}

// ---------------------------------------------------------------------------
// K5: gate + temperature-scaled normalize -> alpha. One block per batch row.
// ---------------------------------------------------------------------------
__global__ void __launch_bounds__(512) k_alpha(
    const float* __restrict__ scores, float* __restrict__ alpha,
    const float* __restrict__ ptau, const float* __restrict__ plam,
    const float* __restrict__ ptemp)
{
    __shared__ float red[16];
    __shared__ float stot;

    int t = threadIdx.x, b = blockIdx.x;
    float tau = *ptau, lam = *plam, invT = 1.f / (*ptemp);

    float4 rv[4];
    float s_local = 0.f;
    const float4* src = (const float4*)(scores + (size_t)b * Nn);
#pragma unroll
    for (int i = 0; i < 4; i++) {
        float4 s4 = src[t + i * 512];
        rv[i].x = __expf(s4.x * invT) * rcp_fma(1.f + __expf(-lam * (s4.x - tau)));
        rv[i].y = __expf(s4.y * invT) * rcp_fma(1.f + __expf(-lam * (s4.y - tau)));
        rv[i].z = __expf(s4.z * invT) * rcp_fma(1.f + __expf(-lam * (s4.z - tau)));
        rv[i].w = __expf(s4.w * invT) * rcp_fma(1.f + __expf(-lam * (s4.w - tau)));
        s_local += (rv[i].x + rv[i].y) + (rv[i].z + rv[i].w);
    }
#pragma unroll
    for (int off = 16; off > 0; off >>= 1)
        s_local += __shfl_xor_sync(0xffffffffu, s_local, off);
    if ((t & 31) == 0) red[t >> 5] = s_local;
    __syncthreads();
    if (t == 0) {
        float s = 0.f;
        for (int w = 0; w < 16; w++) s += red[w];
        stot = s;
    }
    __syncthreads();

    float inv = 1.f / (stot + 1e-8f);
    float4* dst = (float4*)(alpha + (size_t)b * Nn);
#pragma unroll
    for (int i = 0; i < 4; i++)
        dst[t + i * 512] = make_float4(rv[i].x * inv, rv[i].y * inv,
                                       rv[i].z * inv, rv[i].w * inv);
}

// ---------------------------------------------------------------------------
extern "C" void kernel_launch(void* const* d_in, const int* in_sizes, int n_in,
                              void* d_out, int out_size)
{
    const float* z      = (const float*)d_in[0];
    const float* pool   = (const float*)d_in[1];
    const float* WQ     = (const float*)d_in[2];
    const float* WK     = (const float*)d_in[3];
    const float* logits = (const float*)d_in[4];
    const float* tau    = (const float*)d_in[5];
    const float* lam    = (const float*)d_in[6];
    const float* temp   = (const float*)d_in[7];

    float* alpha  = (float*)d_out;
    float* scores = alpha  + (size_t)Bn * Nn;
    float* keys   = scores + (size_t)Bn * Nn;

    __half *BhT, *WQh, *Qh, *Ql, *Kh;
    float *qraw;
    cudaGetSymbolAddress((void**)&BhT,  g_BhT);
    cudaGetSymbolAddress((void**)&WQh,  g_WQh);
    cudaGetSymbolAddress((void**)&Qh,   g_Qh);
    cudaGetSymbolAddress((void**)&Ql,   g_Ql);
    cudaGetSymbolAddress((void**)&Kh,   g_Kh);
    cudaGetSymbolAddress((void**)&qraw, g_qraw);

    // Not a stream op; safe under graph capture; stateless per contract.
    cudaFuncSetAttribute(k_gemm01,
                         cudaFuncAttributeMaxDynamicSharedMemorySize, 131072);
    cudaFuncSetAttribute(k_gemm2,
                         cudaFuncAttributeMaxDynamicSharedMemorySize, 131072);

    // prep: single fused transpose launch for both weight tensors (fp16)
    k_split_T2<<<dim3(Sn, DAn / 64 + Dn / 64), 256>>>(WQ, WQh, WK, BhT);

    // GEMM1 (keys) + GEMM0 (queries) fused into one 136-block wave.
    k_gemm01<<<136, 512, 131072>>>(pool, z, BhT, WQh,
                                   keys, qraw, Kh, Qh, Ql, logits);

    // GEMM2: scores[512,8192] = (Qh+Ql) @ Kh^T
    k_gemm2<<<dim3(Nn / 256, Bn / 128), 512, 131072>>>(Qh, Ql, Kh, scores);

    k_alpha<<<Bn, 512>>>(scores, alpha, tau, lam, temp);
}